// round 2
// baseline (speedup 1.0000x reference)
#include <cuda_runtime.h>

// out[b,c] = dot(x[b,c,:HW], weight[c,:HW]) + bias[c]
// B = 512, C = 512, HW = 784 (float32). HBM-streaming bound (~822 MB of x read once).
// Persistent grid-stride warps, 2 rows per warp per loop iteration for high MLP
// and no block-churn gaps in the DRAM request stream.

#define B_DIM 512
#define C_DIM 512
#define HW_DIM 784
#define HW_VEC4 (HW_DIM / 4)   // 196 float4 per row
#define TOTAL_ROWS (B_DIM * C_DIM)

__global__ __launch_bounds__(256) void scalar_mapping_kernel(
    const float* __restrict__ x,
    const float* __restrict__ weight,
    const float* __restrict__ bias,
    float* __restrict__ out)
{
    const int lane   = threadIdx.x & 31;
    const int warp   = blockIdx.x * (blockDim.x >> 5) + (threadIdx.x >> 5);
    const int nwarps = gridDim.x * (blockDim.x >> 5);

    // Each warp processes pairs of consecutive rows (r, r+1), grid-strided.
    for (int r = warp * 2; r < TOTAL_ROWS; r += nwarps * 2) {
        const int c0 = r & (C_DIM - 1);
        const int c1 = (r + 1) & (C_DIM - 1);

        const float4* __restrict__ x0 =
            reinterpret_cast<const float4*>(x + (size_t)r * HW_DIM);
        const float4* __restrict__ x1 =
            reinterpret_cast<const float4*>(x + (size_t)(r + 1) * HW_DIM);
        const float4* __restrict__ w0 =
            reinterpret_cast<const float4*>(weight + (size_t)c0 * HW_DIM);
        const float4* __restrict__ w1 =
            reinterpret_cast<const float4*>(weight + (size_t)c1 * HW_DIM);

        float s0 = 0.0f, s1 = 0.0f;

        // 196 float4 per row: 6 full warp-iterations + 1 partial (lanes 0-3).
        // Both rows' loads are independent -> ~28 outstanding LDG.128 per thread.
        #pragma unroll
        for (int i = 0; i < 7; ++i) {
            const int idx = lane + i * 32;
            if (idx < HW_VEC4) {
                const float4 xa = __ldcs(&x0[idx]);   // stream x, don't pollute L2
                const float4 wa = __ldg(&w0[idx]);    // weight stays L2-resident
                const float4 xb = __ldcs(&x1[idx]);
                const float4 wb = __ldg(&w1[idx]);
                s0 = fmaf(xa.x, wa.x, s0);
                s0 = fmaf(xa.y, wa.y, s0);
                s0 = fmaf(xa.z, wa.z, s0);
                s0 = fmaf(xa.w, wa.w, s0);
                s1 = fmaf(xb.x, wb.x, s1);
                s1 = fmaf(xb.y, wb.y, s1);
                s1 = fmaf(xb.z, wb.z, s1);
                s1 = fmaf(xb.w, wb.w, s1);
            }
        }

        // Butterfly reduce both sums
        #pragma unroll
        for (int off = 16; off > 0; off >>= 1) {
            s0 += __shfl_xor_sync(0xFFFFFFFFu, s0, off);
            s1 += __shfl_xor_sync(0xFFFFFFFFu, s1, off);
        }

        if (lane == 0) {
            out[r]     = s0 + __ldg(&bias[c0]);
            out[r + 1] = s1 + __ldg(&bias[c1]);
        }
    }
}

extern "C" void kernel_launch(void* const* d_in, const int* in_sizes, int n_in,
                              void* d_out, int out_size)
{
    const float* x      = (const float*)d_in[0];
    const float* weight = (const float*)d_in[1];
    const float* bias   = (const float*)d_in[2];
    float* out          = (float*)d_out;

    // Persistent-ish: 8 blocks per SM on 148 SMs -> 1184 blocks, 256 threads each.
    // 9472 warps grid-stride over 131072 row-pairs (~14 pairs/warp).
    const int blocks = 148 * 8;

    scalar_mapping_kernel<<<blocks, 256>>>(x, weight, bias, out);
}

// round 3
// speedup vs baseline: 1.1478x; 1.1478x over previous
#include <cuda_runtime.h>

// out[b,c] = dot(x[b,c,:HW], weight[c,:HW]) + bias[c]
// B = 512, C = 512, HW = 784 (float32). HBM-streaming bound (~822 MB of x read once).
// R3: R1's launch-ordered block->row mapping (sequential DRAM window) + 2 rows
// per warp as straight-line unrolled code so ptxas front-batches all 14 x-loads.

#define B_DIM 512
#define C_DIM 512
#define HW_DIM 784
#define HW_VEC4 (HW_DIM / 4)        // 196 float4 per row = 6*32 + 4
#define TOTAL_ROWS (B_DIM * C_DIM)  // 262144

__global__ __launch_bounds__(256) void scalar_mapping_kernel(
    const float* __restrict__ x,
    const float* __restrict__ weight,
    const float* __restrict__ bias,
    float* __restrict__ out)
{
    const int lane  = threadIdx.x & 31;
    const int wid   = threadIdx.x >> 5;
    // Block owns 16 consecutive rows; warp owns 2 consecutive rows.
    const int r0 = blockIdx.x * 16 + wid * 2;
    const int r1 = r0 + 1;
    const int c0 = r0 & (C_DIM - 1);
    const int c1 = r1 & (C_DIM - 1);

    const float4* __restrict__ x0 = reinterpret_cast<const float4*>(x + (size_t)r0 * HW_DIM);
    const float4* __restrict__ x1 = reinterpret_cast<const float4*>(x + (size_t)r1 * HW_DIM);
    const float4* __restrict__ w0 = reinterpret_cast<const float4*>(weight + (size_t)c0 * HW_DIM);
    const float4* __restrict__ w1 = reinterpret_cast<const float4*>(weight + (size_t)c1 * HW_DIM);

    // ---- Front-batched x loads (DRAM, streamed) ----
    float4 xa[6], xb[6];
    #pragma unroll
    for (int i = 0; i < 6; ++i) {
        xa[i] = __ldcs(&x0[lane + i * 32]);
        xb[i] = __ldcs(&x1[lane + i * 32]);
    }
    // Tail: elements 192..195 (lanes 0-3 only)
    float4 xat = make_float4(0.f, 0.f, 0.f, 0.f);
    float4 xbt = make_float4(0.f, 0.f, 0.f, 0.f);
    float4 wat = make_float4(0.f, 0.f, 0.f, 0.f);
    float4 wbt = make_float4(0.f, 0.f, 0.f, 0.f);
    if (lane < 4) {
        xat = __ldcs(&x0[192 + lane]);
        xbt = __ldcs(&x1[192 + lane]);
        wat = __ldg(&w0[192 + lane]);
        wbt = __ldg(&w1[192 + lane]);
    }

    // ---- Weight loads (L2-resident) consumed as FMAs retire ----
    float s0 = 0.0f, s1 = 0.0f;
    #pragma unroll
    for (int i = 0; i < 6; ++i) {
        const float4 wa = __ldg(&w0[lane + i * 32]);
        s0 = fmaf(xa[i].x, wa.x, s0);
        s0 = fmaf(xa[i].y, wa.y, s0);
        s0 = fmaf(xa[i].z, wa.z, s0);
        s0 = fmaf(xa[i].w, wa.w, s0);
        const float4 wb = __ldg(&w1[lane + i * 32]);
        s1 = fmaf(xb[i].x, wb.x, s1);
        s1 = fmaf(xb[i].y, wb.y, s1);
        s1 = fmaf(xb[i].z, wb.z, s1);
        s1 = fmaf(xb[i].w, wb.w, s1);
    }
    s0 = fmaf(xat.x, wat.x, s0);
    s0 = fmaf(xat.y, wat.y, s0);
    s0 = fmaf(xat.z, wat.z, s0);
    s0 = fmaf(xat.w, wat.w, s0);
    s1 = fmaf(xbt.x, wbt.x, s1);
    s1 = fmaf(xbt.y, wbt.y, s1);
    s1 = fmaf(xbt.z, wbt.z, s1);
    s1 = fmaf(xbt.w, wbt.w, s1);

    // ---- Butterfly reduce both rows ----
    #pragma unroll
    for (int off = 16; off > 0; off >>= 1) {
        s0 += __shfl_xor_sync(0xFFFFFFFFu, s0, off);
        s1 += __shfl_xor_sync(0xFFFFFFFFu, s1, off);
    }

    if (lane == 0) {
        out[r0] = s0 + __ldg(&bias[c0]);
        out[r1] = s1 + __ldg(&bias[c1]);
    }
}

extern "C" void kernel_launch(void* const* d_in, const int* in_sizes, int n_in,
                              void* d_out, int out_size)
{
    const float* x      = (const float*)d_in[0];
    const float* weight = (const float*)d_in[1];
    const float* bias   = (const float*)d_in[2];
    float* out          = (float*)d_out;

    // 16 rows per block -> 16384 blocks, launched in row order (sequential
    // DRAM window across the concurrently-resident block wave).
    const int blocks = TOTAL_ROWS / 16;

    scalar_mapping_kernel<<<blocks, 256>>>(x, weight, bias, out);
}